// round 9
// baseline (speedup 1.0000x reference)
#include <cuda_runtime.h>

#define Hh 8
#define Bb 8
#define Nn 1024
#define Dd 128
#define Kk 16
#define Ee 128

typedef unsigned long long u64;

// ---------------- f32x2 packed-math helpers --------------------------------
__device__ __forceinline__ u64 pk2(float lo, float hi) {
    u64 r; asm("mov.b64 %0, {%1,%2};" : "=l"(r) : "f"(lo), "f"(hi)); return r;
}
__device__ __forceinline__ void upk2(u64 v, float& lo, float& hi) {
    asm("mov.b64 {%0,%1}, %2;" : "=f"(lo), "=f"(hi) : "l"(v));
}
__device__ __forceinline__ u64 ffma2(u64 a, u64 b, u64 c) {
    u64 d; asm("fma.rn.f32x2 %0, %1, %2, %3;" : "=l"(d) : "l"(a), "l"(b), "l"(c));
    return d;
}
__device__ __forceinline__ u64 fmul2(u64 a, u64 b) {
    u64 d; asm("mul.rn.f32x2 %0, %1, %2;" : "=l"(d) : "l"(a), "l"(b)); return d;
}
__device__ __forceinline__ u64 fadd2(u64 a, u64 b) {
    u64 d; asm("add.rn.f32x2 %0, %1, %2;" : "=l"(d) : "l"(a), "l"(b)); return d;
}
__device__ __forceinline__ float ex2f(float x) {
    float r; asm("ex2.approx.f32 %0, %1;" : "=f"(r) : "f"(x)); return r;
}

// ---------------- scratch (device globals; no allocation) ----------------
__device__ float g_P[8][Hh][Bb][Nn][Kk];        // 8 projections, 33.5MB
__device__ float g_heads_c [Hh][Bb][Nn][Kk];    // 4MB each
__device__ float g_heads_nn[Hh][Bb][Nn][Kk];
__device__ float g_heads_nc[Hh][Bb][Nn][Kk];
__device__ float g_part[3][Hh][Bb][2][Nn][Kk];  // split-KV partial acc, 25MB
__device__ float g_pden[3][Hh][Bb][2][Nn];      // split-KV partial denom
__device__ unsigned g_maskbits[Bb][Nn][Nn / 32]; // 1MB packed mask
__device__ int g_mask_fmt;                       // 0=u8/bool 1=int32 2=float32

// ---------------- mask format sniffer (deterministic, data-driven) -------
__global__ void detect_mask_fmt(const unsigned char* m) {
    __shared__ int mis_nz, big;
    if (threadIdx.x == 0) { mis_nz = 0; big = 0; }
    __syncthreads();
    for (int i = threadIdx.x; i < 4096; i += blockDim.x) {
        unsigned char v = m[i];
        if (v > 1) atomicOr(&big, 1);            // float32 pattern bytes
        if ((i & 3) && v) atomicOr(&mis_nz, 1);  // bool bytes at non-word offsets
    }
    __syncthreads();
    if (threadIdx.x == 0) g_mask_fmt = big ? 2 : (mis_nz ? 0 : 1);
}

// ---------------- mask pack: 1 bit per entry via ballot -------------------
__global__ void pack_mask(const void* mraw) {
    int g = blockIdx.x * blockDim.x + threadIdx.x;  // < B*N*N = 8388608
    int fmt = g_mask_fmt;
    bool bit;
    if (fmt == 0)      bit = ((const unsigned char*)mraw)[g] != 0;
    else if (fmt == 1) bit = ((const int*)mraw)[g] != 0;
    else               bit = ((const float*)mraw)[g] != 0.f;
    unsigned bal = __ballot_sync(0xffffffffu, bit);
    if ((threadIdx.x & 31) == 0) ((unsigned*)g_maskbits)[g >> 5] = bal;
}

// ---------------- projections: P[p][h][row][k] = x_row . W[h][:,k] --------
struct ProjArgs { const float* x[8]; const float* w[8]; };

__global__ __launch_bounds__(128) void proj_kernel(ProjArgs args) {
    const int p   = blockIdx.y;
    const int row = blockIdx.x * 128 + threadIdx.x;   // 0..8191 (= b*1024+n)
    const float* x = args.x[p];
    const float* w = args.w[p];
    __shared__ __align__(16) float Ws[Dd][Kk];  // one head's weight slice

    float4 xr[32];                 // whole input row in registers
    const float4* xrow = (const float4*)(x + (size_t)row * Dd);
#pragma unroll
    for (int i = 0; i < 32; i++) xr[i] = xrow[i];

    for (int h = 0; h < Hh; h++) {
        __syncthreads();
        for (int i = threadIdx.x; i < Dd * Kk; i += 128)
            ((float*)Ws)[i] = w[h * Dd * Kk + i];
        __syncthreads();

        u64 acc2[8];
#pragma unroll
        for (int i = 0; i < 8; i++) acc2[i] = 0ull;

#pragma unroll
        for (int d4 = 0; d4 < 32; d4++) {
            float xv[4] = {xr[d4].x, xr[d4].y, xr[d4].z, xr[d4].w};
#pragma unroll
            for (int j = 0; j < 4; j++) {
                const int d = d4 * 4 + j;
                const ulonglong2* wr = (const ulonglong2*)Ws[d];
                ulonglong2 w01 = wr[0], w23 = wr[1], w45 = wr[2], w67 = wr[3];
                u64 xx = pk2(xv[j], xv[j]);
                acc2[0] = ffma2(xx, w01.x, acc2[0]);
                acc2[1] = ffma2(xx, w01.y, acc2[1]);
                acc2[2] = ffma2(xx, w23.x, acc2[2]);
                acc2[3] = ffma2(xx, w23.y, acc2[3]);
                acc2[4] = ffma2(xx, w45.x, acc2[4]);
                acc2[5] = ffma2(xx, w45.y, acc2[5]);
                acc2[6] = ffma2(xx, w67.x, acc2[6]);
                acc2[7] = ffma2(xx, w67.y, acc2[7]);
            }
        }
        ulonglong2* dst = (ulonglong2*)(&g_P[p][h][0][0][0] + (size_t)row * Kk);
        dst[0] = make_ulonglong2(acc2[0], acc2[1]);
        dst[1] = make_ulonglong2(acc2[2], acc2[3]);
        dst[2] = make_ulonglong2(acc2[4], acc2[5]);
        dst[3] = make_ulonglong2(acc2[6], acc2[7]);
    }
}

// ---------------- attention (split-KV flash, no-max softmax, f32x2) -------
extern __shared__ float s_attn[];

template <bool MASKED>
__device__ __forceinline__ void attn_body(int t, int h, int b, int q0,
                                          int half, float* Ks, float* Vs) {
    // stage this block's 512-key half of K, V into smem
    {
        float4* Ks4 = (float4*)Ks;
        float4* Vs4 = (float4*)Vs;
        const int pk[3] = {6, 1, 3};
        const int pv[3] = {7, 2, 4};
        const float4* Kp4 =
            (const float4*)&g_P[pk[t]][h][b][0][0] + half * 2048;
        const float4* Vp4 =
            (const float4*)&g_P[pv[t]][h][b][0][0] + half * 2048;
        for (int i = threadIdx.x; i < 512 * Kk / 4; i += 256) {
            Ks4[i] = Kp4[i];
            Vs4[i] = Vp4[i];
        }
    }
    __syncthreads();

    const int pq[3] = {5, 0, 0};
    const int qa = q0 + threadIdx.x * 2;     // two queries per thread
    const float* Qp = &g_P[pq[t]][h][b][0][0];

    // scale = norm * log2(e): fold the exp->exp2 conversion into Q
    const float scale = 0.25f * 1.4426950408889634f;

    u64 qA2[8], qB2[8];                      // packed (k, k+1) query pairs
    {
        const float4* a = (const float4*)(Qp + (size_t)qa * Kk);
#pragma unroll
        for (int i = 0; i < 4; i++) {
            float4 va = a[i], vb = a[4 + i];
            qA2[2 * i]     = pk2(va.x * scale, va.y * scale);
            qA2[2 * i + 1] = pk2(va.z * scale, va.w * scale);
            qB2[2 * i]     = pk2(vb.x * scale, vb.y * scale);
            qB2[2 * i + 1] = pk2(vb.z * scale, vb.w * scale);
        }
    }

    u64 accA[8], accB[8];
#pragma unroll
    for (int i = 0; i < 8; i++) { accA[i] = 0ull; accB[i] = 0ull; }
    u64 dab = 0ull;                          // packed (denom_a, denom_b)

    const unsigned* mwa = &g_maskbits[b][qa][0] + half * 16;

    for (int n32 = 0; n32 < 16; n32++) {
        unsigned ma = 0, mb = 0;
        if (MASKED) { ma = mwa[n32]; mb = mwa[32 + n32]; }
#pragma unroll 4
        for (int j = 0; j < 32; j++) {
            const int n = n32 * 32 + j;
            u64 kk2[8];
            {
                const ulonglong2* kr = (const ulonglong2*)(Ks + n * 16);
#pragma unroll
                for (int i = 0; i < 4; i++) {
                    ulonglong2 v = kr[i];
                    kk2[2 * i] = v.x; kk2[2 * i + 1] = v.y;
                }
            }
            u64 sa2 = fmul2(qA2[0], kk2[0]);
            u64 sb2 = fmul2(qB2[0], kk2[0]);
#pragma unroll
            for (int u = 1; u < 8; u++) {
                sa2 = ffma2(qA2[u], kk2[u], sa2);
                sb2 = ffma2(qB2[u], kk2[u], sb2);
            }
            float sal, sah, sbl, sbh;
            upk2(sa2, sal, sah);
            upk2(sb2, sbl, sbh);
            float pa = ex2f(sal + sah);
            float pb = ex2f(sbl + sbh);
            if (MASKED) {
                if ((ma >> j) & 1u) pa = 0.f;
                if ((mb >> j) & 1u) pb = 0.f;
            }
            dab = fadd2(dab, pk2(pa, pb));
            u64 paa = pk2(pa, pa);
            u64 pbb = pk2(pb, pb);
            u64 vv2[8];
            {
                const ulonglong2* vr = (const ulonglong2*)(Vs + n * 16);
#pragma unroll
                for (int i = 0; i < 4; i++) {
                    ulonglong2 v = vr[i];
                    vv2[2 * i] = v.x; vv2[2 * i + 1] = v.y;
                }
            }
#pragma unroll
            for (int u = 0; u < 8; u++) {
                accA[u] = ffma2(paa, vv2[u], accA[u]);
                accB[u] = ffma2(pbb, vv2[u], accB[u]);
            }
        }
    }

    // write unnormalized partials + denominators
    float da, db;
    upk2(dab, da, db);
    float* pout = &g_part[t][h][b][half][qa][0];
    ulonglong2* oa = (ulonglong2*)pout;
#pragma unroll
    for (int i = 0; i < 4; i++) {
        oa[i]     = make_ulonglong2(accA[2 * i], accA[2 * i + 1]);
        oa[4 + i] = make_ulonglong2(accB[2 * i], accB[2 * i + 1]);
    }
    g_pden[t][h][b][half][qa]     = da;
    g_pden[t][h][b][half][qa + 1] = db;
}

__global__ __launch_bounds__(256, 2) void attn_kernel() {
    const int z    = blockIdx.z;       // t*2 + half
    const int t    = z >> 1;           // 0 = color, 1 = nn (masked), 2 = nc
    const int half = z & 1;
    const int hb = blockIdx.y;
    const int h  = hb >> 3;
    const int b  = hb & 7;
    const int q0 = blockIdx.x * 512;
    float* Ks = s_attn;
    float* Vs = s_attn + 512 * Kk;
    if (t == 1) attn_body<true >(t, h, b, q0, half, Ks, Vs);
    else        attn_body<false>(t, h, b, q0, half, Ks, Vs);
}

// ---------------- split-KV combine: sum halves, normalize ------------------
__global__ __launch_bounds__(256) void combine_kernel() {
    const int r = blockIdx.x * 256 + threadIdx.x;   // < 3*64*1024 = 196608
    const int t  = r >> 16;            // / 65536
    const int rem = r & 65535;
    const int hb = rem >> 10;
    const int q  = rem & 1023;
    const int h = hb >> 3, b = hb & 7;

    const float4* p0 = (const float4*)&g_part[t][h][b][0][q][0];
    const float4* p1 = (const float4*)&g_part[t][h][b][1][q][0];
    const float dsum = g_pden[t][h][b][0][q] + g_pden[t][h][b][1][q];
    const float rs = 1.f / dsum;

    float* hout = (t == 0) ? &g_heads_c[0][0][0][0]
                : (t == 1) ? &g_heads_nn[0][0][0][0]
                           : &g_heads_nc[0][0][0][0];
    float4* o = (float4*)(hout + (((size_t)hb) * Nn + q) * Kk);
#pragma unroll
    for (int i = 0; i < 4; i++) {
        float4 a = p0[i], c = p1[i];
        o[i] = make_float4((a.x + c.x) * rs, (a.y + c.y) * rs,
                           (a.z + c.z) * rs, (a.w + c.w) * rs);
    }
}

// ---------------- output projection ---------------------------------------
__global__ __launch_bounds__(256) void outproj_kernel(const float* Wn,
                                                      const float* Wc,
                                                      float* out) {
    const int s    = blockIdx.y;           // 0 = node, 1 = color
    const int row0 = blockIdx.x * 64;      // rows = b*1024+q, 0..8191
    __shared__ __align__(16) float Hs[64][16];
    __shared__ __align__(16) float Ws[16][128];
    const float* W = s ? Wc : Wn;

    const int rg = threadIdx.x >> 4;       // 0..15 -> rows rg*4..+3
    const int cg = threadIdx.x & 15;       // 0..15 -> cols cg*8..+7
    u64 acc2[4][4];
#pragma unroll
    for (int i = 0; i < 4; i++)
#pragma unroll
        for (int j = 0; j < 4; j++) acc2[i][j] = 0ull;

    for (int h = 0; h < Hh; h++) {
        __syncthreads();
        for (int i = threadIdx.x; i < 64 * 16 / 4; i += 256) {
            const int r = i >> 2, v4 = i & 3;
            const size_t f4i = ((size_t)(h * 8192 + row0 + r)) * 4 + v4;
            float4 val;
            if (s == 0) {
                float4 x = ((const float4*)g_heads_nn)[f4i];
                float4 y = ((const float4*)g_heads_nc)[f4i];
                val = make_float4(x.x + y.x, x.y + y.y, x.z + y.z, x.w + y.w);
            } else {
                val = ((const float4*)g_heads_c)[f4i];
            }
            *(float4*)&Hs[r][v4 * 4] = val;
        }
        for (int i = threadIdx.x; i < 16 * 128 / 4; i += 256)
            ((float4*)Ws)[i] = ((const float4*)(W + h * 2048))[i];
        __syncthreads();

#pragma unroll
        for (int v = 0; v < 16; v++) {
            u64 ww[4];
            {
                const ulonglong2* wr0 = (const ulonglong2*)&Ws[v][cg * 8];
                ulonglong2 a = wr0[0], bq = wr0[1];
                ww[0] = a.x; ww[1] = a.y; ww[2] = bq.x; ww[3] = bq.y;
            }
#pragma unroll
            for (int r = 0; r < 4; r++) {
                float hv = Hs[rg * 4 + r][v];
                u64 hh = pk2(hv, hv);
                acc2[r][0] = ffma2(hh, ww[0], acc2[r][0]);
                acc2[r][1] = ffma2(hh, ww[1], acc2[r][1]);
                acc2[r][2] = ffma2(hh, ww[2], acc2[r][2]);
                acc2[r][3] = ffma2(hh, ww[3], acc2[r][3]);
            }
        }
    }

    float* obase = out + (size_t)s * 8192 * 128;
#pragma unroll
    for (int i = 0; i < 4; i++) {
        ulonglong2* o =
            (ulonglong2*)(obase + (size_t)(row0 + rg * 4 + i) * 128 + cg * 8);
        o[0] = make_ulonglong2(acc2[i][0], acc2[i][1]);
        o[1] = make_ulonglong2(acc2[i][2], acc2[i][3]);
    }
}

// ---------------- launch ---------------------------------------------------
extern "C" void kernel_launch(void* const* d_in, const int* in_sizes, int n_in,
                              void* d_out, int out_size) {
    const float* qn   = (const float*)d_in[0];
    const float* qc   = (const float*)d_in[1];
    const void*  mask = d_in[2];

    cudaFuncSetAttribute(attn_kernel,
                         cudaFuncAttributeMaxDynamicSharedMemorySize, 65536);

    ProjArgs pa;
    pa.x[0] = qn; pa.w[0] = (const float*)d_in[3];   // W_query_n
    pa.x[1] = qn; pa.w[1] = (const float*)d_in[4];   // W_key_nn
    pa.x[2] = qn; pa.w[2] = (const float*)d_in[5];   // W_val_nn
    pa.x[3] = qc; pa.w[3] = (const float*)d_in[6];   // W_key_c
    pa.x[4] = qc; pa.w[4] = (const float*)d_in[7];   // W_val_c
    pa.x[5] = qc; pa.w[5] = (const float*)d_in[8];   // W_query_c
    pa.x[6] = qn; pa.w[6] = (const float*)d_in[9];   // W_key_n
    pa.x[7] = qn; pa.w[7] = (const float*)d_in[10];  // W_val_n

    detect_mask_fmt<<<1, 128>>>((const unsigned char*)mask);
    pack_mask<<<32768, 256>>>(mask);
    proj_kernel<<<dim3(64, 8), 128>>>(pa);
    attn_kernel<<<dim3(2, 64, 6), 256, 65536>>>();
    combine_kernel<<<768, 256>>>();
    outproj_kernel<<<dim3(128, 2), 256>>>((const float*)d_in[11],
                                          (const float*)d_in[12],
                                          (float*)d_out);
}

// round 10
// speedup vs baseline: 1.0043x; 1.0043x over previous
#include <cuda_runtime.h>

#define Hh 8
#define Bb 8
#define Nn 1024
#define Dd 128
#define Kk 16
#define Ee 128

typedef unsigned long long u64;

// ---------------- f32x2 packed-math helpers --------------------------------
__device__ __forceinline__ u64 pk2(float lo, float hi) {
    u64 r; asm("mov.b64 %0, {%1,%2};" : "=l"(r) : "f"(lo), "f"(hi)); return r;
}
__device__ __forceinline__ void upk2(u64 v, float& lo, float& hi) {
    asm("mov.b64 {%0,%1}, %2;" : "=f"(lo), "=f"(hi) : "l"(v));
}
__device__ __forceinline__ u64 ffma2(u64 a, u64 b, u64 c) {
    u64 d; asm("fma.rn.f32x2 %0, %1, %2, %3;" : "=l"(d) : "l"(a), "l"(b), "l"(c));
    return d;
}
__device__ __forceinline__ u64 fmul2(u64 a, u64 b) {
    u64 d; asm("mul.rn.f32x2 %0, %1, %2;" : "=l"(d) : "l"(a), "l"(b)); return d;
}
__device__ __forceinline__ u64 fadd2(u64 a, u64 b) {
    u64 d; asm("add.rn.f32x2 %0, %1, %2;" : "=l"(d) : "l"(a), "l"(b)); return d;
}
__device__ __forceinline__ float ex2f(float x) {
    float r; asm("ex2.approx.f32 %0, %1;" : "=f"(r) : "f"(x)); return r;
}

// ---------------- scratch (device globals; no allocation) ----------------
__device__ float g_P[8][Hh][Bb][Nn][Kk];        // 8 projections, 33.5MB
__device__ float g_heads_c [Hh][Bb][Nn][Kk];    // 4MB each
__device__ float g_heads_nn[Hh][Bb][Nn][Kk];
__device__ float g_heads_nc[Hh][Bb][Nn][Kk];
__device__ float g_part[3][Hh][Bb][2][Nn][Kk];  // split-KV partial acc, 25MB
__device__ float g_pden[3][Hh][Bb][2][Nn];      // split-KV partial denom
__device__ unsigned g_maskbits[Bb][Nn][Nn / 32]; // 1MB packed mask
__device__ int g_mask_fmt;                       // 0=u8/bool 1=int32 2=float32

// ---------------- mask format sniffer (deterministic, data-driven) -------
__global__ void detect_mask_fmt(const unsigned char* m) {
    __shared__ int mis_nz, big;
    if (threadIdx.x == 0) { mis_nz = 0; big = 0; }
    __syncthreads();
    for (int i = threadIdx.x; i < 4096; i += blockDim.x) {
        unsigned char v = m[i];
        if (v > 1) atomicOr(&big, 1);            // float32 pattern bytes
        if ((i & 3) && v) atomicOr(&mis_nz, 1);  // bool bytes at non-word offsets
    }
    __syncthreads();
    if (threadIdx.x == 0) g_mask_fmt = big ? 2 : (mis_nz ? 0 : 1);
}

// ---------------- mask pack: 1 bit per entry via ballot -------------------
__global__ void pack_mask(const void* mraw) {
    int g = blockIdx.x * blockDim.x + threadIdx.x;  // < B*N*N = 8388608
    int fmt = g_mask_fmt;
    bool bit;
    if (fmt == 0)      bit = ((const unsigned char*)mraw)[g] != 0;
    else if (fmt == 1) bit = ((const int*)mraw)[g] != 0;
    else               bit = ((const float*)mraw)[g] != 0.f;
    unsigned bal = __ballot_sync(0xffffffffu, bit);
    if ((threadIdx.x & 31) == 0) ((unsigned*)g_maskbits)[g >> 5] = bal;
}

// ---------------- projections: P[p][h][row][k] = x_row . W[h][:,k] --------
struct ProjArgs { const float* x[8]; const float* w[8]; };

__global__ __launch_bounds__(128) void proj_kernel(ProjArgs args) {
    const int p   = blockIdx.y;
    const int row = blockIdx.x * 128 + threadIdx.x;   // 0..8191 (= b*1024+n)
    const float* x = args.x[p];
    const float* w = args.w[p];
    __shared__ __align__(16) float Ws[Dd][Kk];  // one head's weight slice

    float4 xr[32];                 // whole input row in registers
    const float4* xrow = (const float4*)(x + (size_t)row * Dd);
#pragma unroll
    for (int i = 0; i < 32; i++) xr[i] = xrow[i];

    for (int h = 0; h < Hh; h++) {
        __syncthreads();
        for (int i = threadIdx.x; i < Dd * Kk; i += 128)
            ((float*)Ws)[i] = w[h * Dd * Kk + i];
        __syncthreads();

        u64 acc2[8];
#pragma unroll
        for (int i = 0; i < 8; i++) acc2[i] = 0ull;

#pragma unroll
        for (int d4 = 0; d4 < 32; d4++) {
            float xv[4] = {xr[d4].x, xr[d4].y, xr[d4].z, xr[d4].w};
#pragma unroll
            for (int j = 0; j < 4; j++) {
                const int d = d4 * 4 + j;
                const ulonglong2* wr = (const ulonglong2*)Ws[d];
                ulonglong2 w01 = wr[0], w23 = wr[1], w45 = wr[2], w67 = wr[3];
                u64 xx = pk2(xv[j], xv[j]);
                acc2[0] = ffma2(xx, w01.x, acc2[0]);
                acc2[1] = ffma2(xx, w01.y, acc2[1]);
                acc2[2] = ffma2(xx, w23.x, acc2[2]);
                acc2[3] = ffma2(xx, w23.y, acc2[3]);
                acc2[4] = ffma2(xx, w45.x, acc2[4]);
                acc2[5] = ffma2(xx, w45.y, acc2[5]);
                acc2[6] = ffma2(xx, w67.x, acc2[6]);
                acc2[7] = ffma2(xx, w67.y, acc2[7]);
            }
        }
        ulonglong2* dst = (ulonglong2*)(&g_P[p][h][0][0][0] + (size_t)row * Kk);
        dst[0] = make_ulonglong2(acc2[0], acc2[1]);
        dst[1] = make_ulonglong2(acc2[2], acc2[3]);
        dst[2] = make_ulonglong2(acc2[4], acc2[5]);
        dst[3] = make_ulonglong2(acc2[6], acc2[7]);
    }
}

// ---------------- attention (split-KV flash, no-max softmax, f32x2) -------
extern __shared__ float s_attn[];

template <bool MASKED>
__device__ __forceinline__ void attn_body(int t, int h, int b, int q0,
                                          int half, float* Ks, float* Vs) {
    // stage this block's 512-key half of K, V into smem
    {
        float4* Ks4 = (float4*)Ks;
        float4* Vs4 = (float4*)Vs;
        const int pk[3] = {6, 1, 3};
        const int pv[3] = {7, 2, 4};
        const float4* Kp4 =
            (const float4*)&g_P[pk[t]][h][b][0][0] + half * 2048;
        const float4* Vp4 =
            (const float4*)&g_P[pv[t]][h][b][0][0] + half * 2048;
        for (int i = threadIdx.x; i < 512 * Kk / 4; i += 256) {
            Ks4[i] = Kp4[i];
            Vs4[i] = Vp4[i];
        }
    }
    __syncthreads();

    const int pq[3] = {5, 0, 0};
    const int qa = q0 + threadIdx.x * 2;     // two queries per thread
    const float* Qp = &g_P[pq[t]][h][b][0][0];

    // scale = norm * log2(e): fold the exp->exp2 conversion into Q
    const float scale = 0.25f * 1.4426950408889634f;

    u64 qA2[8], qB2[8];                      // packed (k, k+1) query pairs
    {
        const float4* a = (const float4*)(Qp + (size_t)qa * Kk);
#pragma unroll
        for (int i = 0; i < 4; i++) {
            float4 va = a[i], vb = a[4 + i];
            qA2[2 * i]     = pk2(va.x * scale, va.y * scale);
            qA2[2 * i + 1] = pk2(va.z * scale, va.w * scale);
            qB2[2 * i]     = pk2(vb.x * scale, vb.y * scale);
            qB2[2 * i + 1] = pk2(vb.z * scale, vb.w * scale);
        }
    }

    u64 accA[8], accB[8];
#pragma unroll
    for (int i = 0; i < 8; i++) { accA[i] = 0ull; accB[i] = 0ull; }
    u64 dab = 0ull;                          // packed (denom_a, denom_b)

    const unsigned* mwa = &g_maskbits[b][qa][0] + half * 16;

    for (int n32 = 0; n32 < 16; n32++) {
        unsigned ma = 0, mb = 0;
        if (MASKED) { ma = mwa[n32]; mb = mwa[32 + n32]; }
#pragma unroll 4
        for (int j = 0; j < 32; j++) {
            const int n = n32 * 32 + j;
            u64 kk2[8];
            {
                const ulonglong2* kr = (const ulonglong2*)(Ks + n * 16);
#pragma unroll
                for (int i = 0; i < 4; i++) {
                    ulonglong2 v = kr[i];
                    kk2[2 * i] = v.x; kk2[2 * i + 1] = v.y;
                }
            }
            u64 sa2 = fmul2(qA2[0], kk2[0]);
            u64 sb2 = fmul2(qB2[0], kk2[0]);
#pragma unroll
            for (int u = 1; u < 8; u++) {
                sa2 = ffma2(qA2[u], kk2[u], sa2);
                sb2 = ffma2(qB2[u], kk2[u], sb2);
            }
            float sal, sah, sbl, sbh;
            upk2(sa2, sal, sah);
            upk2(sb2, sbl, sbh);
            float pa = ex2f(sal + sah);
            float pb = ex2f(sbl + sbh);
            if (MASKED) {
                if ((ma >> j) & 1u) pa = 0.f;
                if ((mb >> j) & 1u) pb = 0.f;
            }
            dab = fadd2(dab, pk2(pa, pb));
            u64 paa = pk2(pa, pa);
            u64 pbb = pk2(pb, pb);
            u64 vv2[8];
            {
                const ulonglong2* vr = (const ulonglong2*)(Vs + n * 16);
#pragma unroll
                for (int i = 0; i < 4; i++) {
                    ulonglong2 v = vr[i];
                    vv2[2 * i] = v.x; vv2[2 * i + 1] = v.y;
                }
            }
#pragma unroll
            for (int u = 0; u < 8; u++) {
                accA[u] = ffma2(paa, vv2[u], accA[u]);
                accB[u] = ffma2(pbb, vv2[u], accB[u]);
            }
        }
    }

    // write unnormalized partials + denominators
    float da, db;
    upk2(dab, da, db);
    float* pout = &g_part[t][h][b][half][qa][0];
    ulonglong2* oa = (ulonglong2*)pout;
#pragma unroll
    for (int i = 0; i < 4; i++) {
        oa[i]     = make_ulonglong2(accA[2 * i], accA[2 * i + 1]);
        oa[4 + i] = make_ulonglong2(accB[2 * i], accB[2 * i + 1]);
    }
    g_pden[t][h][b][half][qa]     = da;
    g_pden[t][h][b][half][qa + 1] = db;
}

__global__ __launch_bounds__(256, 2) void attn_kernel() {
    const int z    = blockIdx.z;       // t*2 + half
    const int t    = z >> 1;           // 0 = color, 1 = nn (masked), 2 = nc
    const int half = z & 1;
    const int hb = blockIdx.y;
    const int h  = hb >> 3;
    const int b  = hb & 7;
    const int q0 = blockIdx.x * 512;
    float* Ks = s_attn;
    float* Vs = s_attn + 512 * Kk;
    if (t == 1) attn_body<true >(t, h, b, q0, half, Ks, Vs);
    else        attn_body<false>(t, h, b, q0, half, Ks, Vs);
}

// ---------------- split-KV combine: sum halves, normalize ------------------
__global__ __launch_bounds__(256) void combine_kernel() {
    const int r = blockIdx.x * 256 + threadIdx.x;   // < 3*64*1024 = 196608
    const int t  = r >> 16;            // / 65536
    const int rem = r & 65535;
    const int hb = rem >> 10;
    const int q  = rem & 1023;
    const int h = hb >> 3, b = hb & 7;

    const float4* p0 = (const float4*)&g_part[t][h][b][0][q][0];
    const float4* p1 = (const float4*)&g_part[t][h][b][1][q][0];
    const float dsum = g_pden[t][h][b][0][q] + g_pden[t][h][b][1][q];
    const float rs = 1.f / dsum;

    float* hout = (t == 0) ? &g_heads_c[0][0][0][0]
                : (t == 1) ? &g_heads_nn[0][0][0][0]
                           : &g_heads_nc[0][0][0][0];
    float4* o = (float4*)(hout + (((size_t)hb) * Nn + q) * Kk);
#pragma unroll
    for (int i = 0; i < 4; i++) {
        float4 a = p0[i], c = p1[i];
        o[i] = make_float4((a.x + c.x) * rs, (a.y + c.y) * rs,
                           (a.z + c.z) * rs, (a.w + c.w) * rs);
    }
}

// ---------------- output projection ---------------------------------------
__global__ __launch_bounds__(256) void outproj_kernel(const float* Wn,
                                                      const float* Wc,
                                                      float* out) {
    const int s    = blockIdx.y;           // 0 = node, 1 = color
    const int row0 = blockIdx.x * 64;      // rows = b*1024+q, 0..8191
    __shared__ __align__(16) float Hs[64][16];
    __shared__ __align__(16) float Ws[16][128];
    const float* W = s ? Wc : Wn;

    const int rg = threadIdx.x >> 4;       // 0..15 -> rows rg*4..+3
    const int cg = threadIdx.x & 15;       // 0..15 -> cols cg*8..+7
    u64 acc2[4][4];
#pragma unroll
    for (int i = 0; i < 4; i++)
#pragma unroll
        for (int j = 0; j < 4; j++) acc2[i][j] = 0ull;

    for (int h = 0; h < Hh; h++) {
        __syncthreads();
        for (int i = threadIdx.x; i < 64 * 16 / 4; i += 256) {
            const int r = i >> 2, v4 = i & 3;
            const size_t f4i = ((size_t)(h * 8192 + row0 + r)) * 4 + v4;
            float4 val;
            if (s == 0) {
                float4 x = ((const float4*)g_heads_nn)[f4i];
                float4 y = ((const float4*)g_heads_nc)[f4i];
                val = make_float4(x.x + y.x, x.y + y.y, x.z + y.z, x.w + y.w);
            } else {
                val = ((const float4*)g_heads_c)[f4i];
            }
            *(float4*)&Hs[r][v4 * 4] = val;
        }
        for (int i = threadIdx.x; i < 16 * 128 / 4; i += 256)
            ((float4*)Ws)[i] = ((const float4*)(W + h * 2048))[i];
        __syncthreads();

#pragma unroll
        for (int v = 0; v < 16; v++) {
            u64 ww[4];
            {
                const ulonglong2* wr0 = (const ulonglong2*)&Ws[v][cg * 8];
                ulonglong2 a = wr0[0], bq = wr0[1];
                ww[0] = a.x; ww[1] = a.y; ww[2] = bq.x; ww[3] = bq.y;
            }
#pragma unroll
            for (int r = 0; r < 4; r++) {
                float hv = Hs[rg * 4 + r][v];
                u64 hh = pk2(hv, hv);
                acc2[r][0] = ffma2(hh, ww[0], acc2[r][0]);
                acc2[r][1] = ffma2(hh, ww[1], acc2[r][1]);
                acc2[r][2] = ffma2(hh, ww[2], acc2[r][2]);
                acc2[r][3] = ffma2(hh, ww[3], acc2[r][3]);
            }
        }
    }

    float* obase = out + (size_t)s * 8192 * 128;
#pragma unroll
    for (int i = 0; i < 4; i++) {
        ulonglong2* o =
            (ulonglong2*)(obase + (size_t)(row0 + rg * 4 + i) * 128 + cg * 8);
        o[0] = make_ulonglong2(acc2[i][0], acc2[i][1]);
        o[1] = make_ulonglong2(acc2[i][2], acc2[i][3]);
    }
}

// ---------------- launch ---------------------------------------------------
extern "C" void kernel_launch(void* const* d_in, const int* in_sizes, int n_in,
                              void* d_out, int out_size) {
    const float* qn   = (const float*)d_in[0];
    const float* qc   = (const float*)d_in[1];
    const void*  mask = d_in[2];

    cudaFuncSetAttribute(attn_kernel,
                         cudaFuncAttributeMaxDynamicSharedMemorySize, 65536);

    ProjArgs pa;
    pa.x[0] = qn; pa.w[0] = (const float*)d_in[3];   // W_query_n
    pa.x[1] = qn; pa.w[1] = (const float*)d_in[4];   // W_key_nn
    pa.x[2] = qn; pa.w[2] = (const float*)d_in[5];   // W_val_nn
    pa.x[3] = qc; pa.w[3] = (const float*)d_in[6];   // W_key_c
    pa.x[4] = qc; pa.w[4] = (const float*)d_in[7];   // W_val_c
    pa.x[5] = qc; pa.w[5] = (const float*)d_in[8];   // W_query_c
    pa.x[6] = qn; pa.w[6] = (const float*)d_in[9];   // W_key_n
    pa.x[7] = qn; pa.w[7] = (const float*)d_in[10];  // W_val_n

    detect_mask_fmt<<<1, 128>>>((const unsigned char*)mask);
    pack_mask<<<32768, 256>>>(mask);
    proj_kernel<<<dim3(64, 8), 128>>>(pa);
    attn_kernel<<<dim3(2, 64, 6), 256, 65536>>>();
    combine_kernel<<<768, 256>>>();
    outproj_kernel<<<dim3(128, 2), 256>>>((const float*)d_in[11],
                                          (const float*)d_in[12],
                                          (float*)d_out);
}

// round 11
// speedup vs baseline: 1.0076x; 1.0033x over previous
#include <cuda_runtime.h>

#define Hh 8
#define Bb 8
#define Nn 1024
#define Dd 128
#define Kk 16
#define Ee 128

typedef unsigned long long u64;

// ---------------- f32x2 packed-math helpers --------------------------------
__device__ __forceinline__ u64 pk2(float lo, float hi) {
    u64 r; asm("mov.b64 %0, {%1,%2};" : "=l"(r) : "f"(lo), "f"(hi)); return r;
}
__device__ __forceinline__ void upk2(u64 v, float& lo, float& hi) {
    asm("mov.b64 {%0,%1}, %2;" : "=f"(lo), "=f"(hi) : "l"(v));
}
__device__ __forceinline__ u64 ffma2(u64 a, u64 b, u64 c) {
    u64 d; asm("fma.rn.f32x2 %0, %1, %2, %3;" : "=l"(d) : "l"(a), "l"(b), "l"(c));
    return d;
}
__device__ __forceinline__ u64 fmul2(u64 a, u64 b) {
    u64 d; asm("mul.rn.f32x2 %0, %1, %2;" : "=l"(d) : "l"(a), "l"(b)); return d;
}
__device__ __forceinline__ u64 fadd2(u64 a, u64 b) {
    u64 d; asm("add.rn.f32x2 %0, %1, %2;" : "=l"(d) : "l"(a), "l"(b)); return d;
}
__device__ __forceinline__ float ex2f(float x) {
    float r; asm("ex2.approx.f32 %0, %1;" : "=f"(r) : "f"(x)); return r;
}

// ---------------- scratch (device globals; no allocation) ----------------
__device__ float g_P[8][Hh][Bb][Nn][Kk];        // 8 projections, 33.5MB
__device__ float g_heads_c [Hh][Bb][Nn][Kk];    // 4MB each
__device__ float g_heads_nn[Hh][Bb][Nn][Kk];
__device__ float g_heads_nc[Hh][Bb][Nn][Kk];
__device__ float g_part[3][Hh][Bb][2][Nn][Kk];  // split-KV partial acc, 25MB
__device__ float g_pden[3][Hh][Bb][2][Nn];      // split-KV partial denom
__device__ unsigned g_maskbits[Bb][Nn][Nn / 32]; // 1MB packed mask
__device__ int g_mask_fmt;                       // 0=u8/bool 1=int32 2=float32

// ---------------- mask format sniffer (deterministic, data-driven) -------
__global__ void detect_mask_fmt(const unsigned char* m) {
    __shared__ int mis_nz, big;
    if (threadIdx.x == 0) { mis_nz = 0; big = 0; }
    __syncthreads();
    for (int i = threadIdx.x; i < 4096; i += blockDim.x) {
        unsigned char v = m[i];
        if (v > 1) atomicOr(&big, 1);            // float32 pattern bytes
        if ((i & 3) && v) atomicOr(&mis_nz, 1);  // bool bytes at non-word offsets
    }
    __syncthreads();
    if (threadIdx.x == 0) g_mask_fmt = big ? 2 : (mis_nz ? 0 : 1);
}

// ---------------- mask pack: 1 bit per entry via ballot -------------------
__global__ void pack_mask(const void* mraw) {
    int g = blockIdx.x * blockDim.x + threadIdx.x;  // < B*N*N = 8388608
    int fmt = g_mask_fmt;
    bool bit;
    if (fmt == 0)      bit = ((const unsigned char*)mraw)[g] != 0;
    else if (fmt == 1) bit = ((const int*)mraw)[g] != 0;
    else               bit = ((const float*)mraw)[g] != 0.f;
    unsigned bal = __ballot_sync(0xffffffffu, bit);
    if ((threadIdx.x & 31) == 0) ((unsigned*)g_maskbits)[g >> 5] = bal;
}

// ---------------- projections: P[p][h][row][k] = x_row . W[h][:,k] --------
struct ProjArgs { const float* x[8]; const float* w[8]; };

__global__ __launch_bounds__(128) void proj_kernel(ProjArgs args) {
    const int p   = blockIdx.y;
    const int row = blockIdx.x * 128 + threadIdx.x;   // 0..8191 (= b*1024+n)
    const float* x = args.x[p];
    const float* w = args.w[p];
    __shared__ __align__(16) float Ws[Dd][Kk];  // one head's weight slice

    float4 xr[32];                 // whole input row in registers
    const float4* xrow = (const float4*)(x + (size_t)row * Dd);
#pragma unroll
    for (int i = 0; i < 32; i++) xr[i] = xrow[i];

    for (int h = 0; h < Hh; h++) {
        __syncthreads();
        for (int i = threadIdx.x; i < Dd * Kk; i += 128)
            ((float*)Ws)[i] = w[h * Dd * Kk + i];
        __syncthreads();

        u64 acc2[8];
#pragma unroll
        for (int i = 0; i < 8; i++) acc2[i] = 0ull;

#pragma unroll
        for (int d4 = 0; d4 < 32; d4++) {
            float xv[4] = {xr[d4].x, xr[d4].y, xr[d4].z, xr[d4].w};
#pragma unroll
            for (int j = 0; j < 4; j++) {
                const int d = d4 * 4 + j;
                const ulonglong2* wr = (const ulonglong2*)Ws[d];
                ulonglong2 w01 = wr[0], w23 = wr[1], w45 = wr[2], w67 = wr[3];
                u64 xx = pk2(xv[j], xv[j]);
                acc2[0] = ffma2(xx, w01.x, acc2[0]);
                acc2[1] = ffma2(xx, w01.y, acc2[1]);
                acc2[2] = ffma2(xx, w23.x, acc2[2]);
                acc2[3] = ffma2(xx, w23.y, acc2[3]);
                acc2[4] = ffma2(xx, w45.x, acc2[4]);
                acc2[5] = ffma2(xx, w45.y, acc2[5]);
                acc2[6] = ffma2(xx, w67.x, acc2[6]);
                acc2[7] = ffma2(xx, w67.y, acc2[7]);
            }
        }
        ulonglong2* dst = (ulonglong2*)(&g_P[p][h][0][0][0] + (size_t)row * Kk);
        dst[0] = make_ulonglong2(acc2[0], acc2[1]);
        dst[1] = make_ulonglong2(acc2[2], acc2[3]);
        dst[2] = make_ulonglong2(acc2[4], acc2[5]);
        dst[3] = make_ulonglong2(acc2[6], acc2[7]);
    }
}

// ---------------- attention (split-KV flash, no-max softmax, f32x2) -------
extern __shared__ float s_attn[];

template <bool MASKED>
__device__ __forceinline__ void attn_body(int t, int h, int b, int q0,
                                          int half, float* Ks, float* Vs) {
    // stage this block's 512-key half of K, V into smem
    {
        float4* Ks4 = (float4*)Ks;
        float4* Vs4 = (float4*)Vs;
        const int pk[3] = {6, 1, 3};
        const int pv[3] = {7, 2, 4};
        const float4* Kp4 =
            (const float4*)&g_P[pk[t]][h][b][0][0] + half * 2048;
        const float4* Vp4 =
            (const float4*)&g_P[pv[t]][h][b][0][0] + half * 2048;
        for (int i = threadIdx.x; i < 512 * Kk / 4; i += 256) {
            Ks4[i] = Kp4[i];
            Vs4[i] = Vp4[i];
        }
    }
    __syncthreads();

    const int pq[3] = {5, 0, 0};
    const int qa = q0 + threadIdx.x * 2;     // two queries per thread
    const float* Qp = &g_P[pq[t]][h][b][0][0];

    // scale = norm * log2(e): fold the exp->exp2 conversion into Q
    const float scale = 0.25f * 1.4426950408889634f;

    u64 qA2[8], qB2[8];                      // packed (k, k+1) query pairs
    {
        const float4* a = (const float4*)(Qp + (size_t)qa * Kk);
#pragma unroll
        for (int i = 0; i < 4; i++) {
            float4 va = a[i], vb = a[4 + i];
            qA2[2 * i]     = pk2(va.x * scale, va.y * scale);
            qA2[2 * i + 1] = pk2(va.z * scale, va.w * scale);
            qB2[2 * i]     = pk2(vb.x * scale, vb.y * scale);
            qB2[2 * i + 1] = pk2(vb.z * scale, vb.w * scale);
        }
    }

    u64 accA[8], accB[8];
#pragma unroll
    for (int i = 0; i < 8; i++) { accA[i] = 0ull; accB[i] = 0ull; }
    u64 dab = 0ull;                          // packed (denom_a, denom_b)

    const unsigned* mwa = &g_maskbits[b][qa][0] + half * 16;

    for (int n32 = 0; n32 < 16; n32++) {
        unsigned ma = 0, mb = 0;
        if (MASKED) { ma = mwa[n32]; mb = mwa[32 + n32]; }
#pragma unroll 4
        for (int j = 0; j < 32; j++) {
            const int n = n32 * 32 + j;
            u64 kk2[8];
            {
                const ulonglong2* kr = (const ulonglong2*)(Ks + n * 16);
#pragma unroll
                for (int i = 0; i < 4; i++) {
                    ulonglong2 v = kr[i];
                    kk2[2 * i] = v.x; kk2[2 * i + 1] = v.y;
                }
            }
            u64 sa2 = fmul2(qA2[0], kk2[0]);
            u64 sb2 = fmul2(qB2[0], kk2[0]);
#pragma unroll
            for (int u = 1; u < 8; u++) {
                sa2 = ffma2(qA2[u], kk2[u], sa2);
                sb2 = ffma2(qB2[u], kk2[u], sb2);
            }
            float sal, sah, sbl, sbh;
            upk2(sa2, sal, sah);
            upk2(sb2, sbl, sbh);
            float pa = ex2f(sal + sah);
            float pb = ex2f(sbl + sbh);
            if (MASKED) {
                if ((ma >> j) & 1u) pa = 0.f;
                if ((mb >> j) & 1u) pb = 0.f;
            }
            dab = fadd2(dab, pk2(pa, pb));
            u64 paa = pk2(pa, pa);
            u64 pbb = pk2(pb, pb);
            u64 vv2[8];
            {
                const ulonglong2* vr = (const ulonglong2*)(Vs + n * 16);
#pragma unroll
                for (int i = 0; i < 4; i++) {
                    ulonglong2 v = vr[i];
                    vv2[2 * i] = v.x; vv2[2 * i + 1] = v.y;
                }
            }
#pragma unroll
            for (int u = 0; u < 8; u++) {
                accA[u] = ffma2(paa, vv2[u], accA[u]);
                accB[u] = ffma2(pbb, vv2[u], accB[u]);
            }
        }
    }

    // write unnormalized partials + denominators
    float da, db;
    upk2(dab, da, db);
    float* pout = &g_part[t][h][b][half][qa][0];
    ulonglong2* oa = (ulonglong2*)pout;
#pragma unroll
    for (int i = 0; i < 4; i++) {
        oa[i]     = make_ulonglong2(accA[2 * i], accA[2 * i + 1]);
        oa[4 + i] = make_ulonglong2(accB[2 * i], accB[2 * i + 1]);
    }
    g_pden[t][h][b][half][qa]     = da;
    g_pden[t][h][b][half][qa + 1] = db;
}

__global__ __launch_bounds__(256, 2) void attn_kernel() {
    const int z    = blockIdx.z;       // t*2 + half
    const int t    = z >> 1;           // 0 = color, 1 = nn (masked), 2 = nc
    const int half = z & 1;
    const int hb = blockIdx.y;
    const int h  = hb >> 3;
    const int b  = hb & 7;
    const int q0 = blockIdx.x * 512;
    float* Ks = s_attn;
    float* Vs = s_attn + 512 * Kk;
    if (t == 1) attn_body<true >(t, h, b, q0, half, Ks, Vs);
    else        attn_body<false>(t, h, b, q0, half, Ks, Vs);
}

// ---------------- split-KV combine: sum halves, normalize ------------------
__global__ __launch_bounds__(256) void combine_kernel() {
    const int r = blockIdx.x * 256 + threadIdx.x;   // < 3*64*1024 = 196608
    const int t  = r >> 16;            // / 65536
    const int rem = r & 65535;
    const int hb = rem >> 10;
    const int q  = rem & 1023;
    const int h = hb >> 3, b = hb & 7;

    const float4* p0 = (const float4*)&g_part[t][h][b][0][q][0];
    const float4* p1 = (const float4*)&g_part[t][h][b][1][q][0];
    const float dsum = g_pden[t][h][b][0][q] + g_pden[t][h][b][1][q];
    const float rs = 1.f / dsum;

    float* hout = (t == 0) ? &g_heads_c[0][0][0][0]
                : (t == 1) ? &g_heads_nn[0][0][0][0]
                           : &g_heads_nc[0][0][0][0];
    float4* o = (float4*)(hout + (((size_t)hb) * Nn + q) * Kk);
#pragma unroll
    for (int i = 0; i < 4; i++) {
        float4 a = p0[i], c = p1[i];
        o[i] = make_float4((a.x + c.x) * rs, (a.y + c.y) * rs,
                           (a.z + c.z) * rs, (a.w + c.w) * rs);
    }
}

// ---------------- output projection ---------------------------------------
__global__ __launch_bounds__(256) void outproj_kernel(const float* Wn,
                                                      const float* Wc,
                                                      float* out) {
    const int s    = blockIdx.y;           // 0 = node, 1 = color
    const int row0 = blockIdx.x * 64;      // rows = b*1024+q, 0..8191
    __shared__ __align__(16) float Hs[64][16];
    __shared__ __align__(16) float Ws[16][128];
    const float* W = s ? Wc : Wn;

    const int rg = threadIdx.x >> 4;       // 0..15 -> rows rg*4..+3
    const int cg = threadIdx.x & 15;       // 0..15 -> cols cg*8..+7
    u64 acc2[4][4];
#pragma unroll
    for (int i = 0; i < 4; i++)
#pragma unroll
        for (int j = 0; j < 4; j++) acc2[i][j] = 0ull;

    for (int h = 0; h < Hh; h++) {
        __syncthreads();
        for (int i = threadIdx.x; i < 64 * 16 / 4; i += 256) {
            const int r = i >> 2, v4 = i & 3;
            const size_t f4i = ((size_t)(h * 8192 + row0 + r)) * 4 + v4;
            float4 val;
            if (s == 0) {
                float4 x = ((const float4*)g_heads_nn)[f4i];
                float4 y = ((const float4*)g_heads_nc)[f4i];
                val = make_float4(x.x + y.x, x.y + y.y, x.z + y.z, x.w + y.w);
            } else {
                val = ((const float4*)g_heads_c)[f4i];
            }
            *(float4*)&Hs[r][v4 * 4] = val;
        }
        for (int i = threadIdx.x; i < 16 * 128 / 4; i += 256)
            ((float4*)Ws)[i] = ((const float4*)(W + h * 2048))[i];
        __syncthreads();

#pragma unroll
        for (int v = 0; v < 16; v++) {
            u64 ww[4];
            {
                const ulonglong2* wr0 = (const ulonglong2*)&Ws[v][cg * 8];
                ulonglong2 a = wr0[0], bq = wr0[1];
                ww[0] = a.x; ww[1] = a.y; ww[2] = bq.x; ww[3] = bq.y;
            }
#pragma unroll
            for (int r = 0; r < 4; r++) {
                float hv = Hs[rg * 4 + r][v];
                u64 hh = pk2(hv, hv);
                acc2[r][0] = ffma2(hh, ww[0], acc2[r][0]);
                acc2[r][1] = ffma2(hh, ww[1], acc2[r][1]);
                acc2[r][2] = ffma2(hh, ww[2], acc2[r][2]);
                acc2[r][3] = ffma2(hh, ww[3], acc2[r][3]);
            }
        }
    }

    float* obase = out + (size_t)s * 8192 * 128;
#pragma unroll
    for (int i = 0; i < 4; i++) {
        ulonglong2* o =
            (ulonglong2*)(obase + (size_t)(row0 + rg * 4 + i) * 128 + cg * 8);
        o[0] = make_ulonglong2(acc2[i][0], acc2[i][1]);
        o[1] = make_ulonglong2(acc2[i][2], acc2[i][3]);
    }
}

// ---------------- launch ---------------------------------------------------
extern "C" void kernel_launch(void* const* d_in, const int* in_sizes, int n_in,
                              void* d_out, int out_size) {
    const float* qn   = (const float*)d_in[0];
    const float* qc   = (const float*)d_in[1];
    const void*  mask = d_in[2];

    cudaFuncSetAttribute(attn_kernel,
                         cudaFuncAttributeMaxDynamicSharedMemorySize, 65536);

    ProjArgs pa;
    pa.x[0] = qn; pa.w[0] = (const float*)d_in[3];   // W_query_n
    pa.x[1] = qn; pa.w[1] = (const float*)d_in[4];   // W_key_nn
    pa.x[2] = qn; pa.w[2] = (const float*)d_in[5];   // W_val_nn
    pa.x[3] = qc; pa.w[3] = (const float*)d_in[6];   // W_key_c
    pa.x[4] = qc; pa.w[4] = (const float*)d_in[7];   // W_val_c
    pa.x[5] = qc; pa.w[5] = (const float*)d_in[8];   // W_query_c
    pa.x[6] = qn; pa.w[6] = (const float*)d_in[9];   // W_key_n
    pa.x[7] = qn; pa.w[7] = (const float*)d_in[10];  // W_val_n

    detect_mask_fmt<<<1, 128>>>((const unsigned char*)mask);
    pack_mask<<<32768, 256>>>(mask);
    proj_kernel<<<dim3(64, 8), 128>>>(pa);
    attn_kernel<<<dim3(2, 64, 6), 256, 65536>>>();
    combine_kernel<<<768, 256>>>();
    outproj_kernel<<<dim3(128, 2), 256>>>((const float*)d_in[11],
                                          (const float*)d_in[12],
                                          (float*)d_out);
}